// round 15
// baseline (speedup 1.0000x reference)
#include <stdint.h>
#include <cstdint>
#include <cuda_runtime.h>
#include <cuda_bf16.h>
#include <math.h>
#include <float.h>

// Problem dims
#define NB 128
#define ND 256
#define NS 512
#define NK 50
#define NH 256
#define NROWS (NB*NS)            // 65536 (b,s) rows
#define OUT_PRED 0
#define OUT_SCAL0 256
#define OUT_SIM 257
#define OUT_FAR 258
#define OUT_NN 259               // B*S*K floats
#define OUT_AE (259 + NROWS*NK)

typedef unsigned long long ull;

// ---------------- packed f32x2 helpers (FFMA2) ----------------
__device__ __forceinline__ ull pack_dup(float a) {
    ull r; asm("mov.b64 %0, {%1, %1};" : "=l"(r) : "f"(a)); return r;
}
__device__ __forceinline__ void ffma2(ull &c, ull a, ull b) {
    asm("fma.rn.f32x2 %0, %1, %2, %0;" : "+l"(c) : "l"(a), "l"(b));
}
__device__ __forceinline__ float2 unpack2(ull v) {
    float2 f; asm("mov.b64 {%0, %1}, %2;" : "=f"(f.x), "=f"(f.y) : "l"(v)); return f;
}

// ---------------- warp MMA m16n8k16 bf16 (baseline PTX, HMMA on tensor pipe) ----------------
__device__ __forceinline__ void mma16816(float* c, const uint32_t* a, const uint32_t* b) {
    asm volatile("mma.sync.aligned.m16n8k16.row.col.f32.bf16.bf16.f32 "
        "{%0,%1,%2,%3}, {%4,%5,%6,%7}, {%8,%9}, {%0,%1,%2,%3};"
        : "+f"(c[0]), "+f"(c[1]), "+f"(c[2]), "+f"(c[3])
        : "r"(a[0]), "r"(a[1]), "r"(a[2]), "r"(a[3]), "r"(b[0]), "r"(b[1]));
}

// ---------------- bf16 split helpers ----------------
__device__ __forceinline__ void split_bf16(float v, unsigned short &h, unsigned short &l) {
    __nv_bfloat16 hb = __float2bfloat16(v);
    float r = v - __bfloat162float(hb);
    __nv_bfloat16 lb = __float2bfloat16(r);
    h = *(unsigned short*)&hb;
    l = *(unsigned short*)&lb;
}

// ---------------- device scratch ----------------
#define TSEL_CAP 16384
__device__ __align__(16) float g_tvn[ND*NK];
__device__ __align__(16) float g_tvnp[ND*64];     // padded [D][64]
__device__ __align__(16) float g_invnorm[NROWS];
__device__ __align__(16) float g_tpnT[NK*NROWS];  // [K][B*S]
__device__ __align__(16) float g_nnT[NK*NROWS];   // nn transposed [K][B*S]
__device__ __align__(16) unsigned short g_rec1h[NROWS*NH];  // bf16 hi of relu(nn@rv1)
__device__ __align__(16) unsigned short g_rec1l[NROWS*NH];  // bf16 lo
__device__ __align__(16) unsigned short g_rv2hT[ND*NH];     // bf16 hi of rv2^T  [n][k]
__device__ __align__(16) unsigned short g_rv2lT[ND*NH];     // bf16 lo
__device__ __align__(16) float g_h1sum[NB*NH];    // sum_s rec1[b,s,h]
__device__ __align__(16) float g_mean[NB*ND];
__device__ __align__(16) unsigned g_hist[NK*4096];
__device__ __align__(16) float g_bndbuf[NK*TSEL_CAP];
__device__ unsigned g_bndcnt[NK];
__device__ unsigned g_T[NK];
__device__ unsigned g_cntAbove[NK];
__device__ float g_ae;
__device__ float g_sim;
__device__ float g_far;

// ---------------- kernel 0: prep ----------------
__global__ void prep_kernel(const float* __restrict__ tv) {
    __shared__ float inv[64];
    __shared__ float red[256];
    int tid = threadIdx.x;
    if (tid < NK) {
        float ss = 0.f;
        for (int d = 0; d < ND; d++) { float v = tv[d*NK + tid]; ss += v*v; }
        inv[tid] = 1.0f / fmaxf(sqrtf(ss), 1e-12f);
    }
    __syncthreads();
    for (int i = tid; i < ND*NK; i += 256) g_tvn[i] = tv[i] * inv[i % NK];
    for (int i = tid; i < NB*NH; i += 256) g_h1sum[i] = 0.f;
    if (tid == 0) { g_ae = 0.f; g_sim = 0.f; }
    __syncthreads();
    for (int i = tid; i < ND*64; i += 256) {
        int d = i >> 6, k = i & 63;
        g_tvnp[i] = (k < NK) ? g_tvn[d*NK + k] : 0.f;
    }
    float acc = 0.f;
    for (int p = tid; p < NK*NK; p += 256) {
        int i = p / NK, j = p % NK;
        float ds = 0.f;
        for (int d = 0; d < ND; d++) ds += g_tvn[d*NK + i] * g_tvn[d*NK + j];
        acc += ds - ((i == j) ? 1.0f : 0.0f);
    }
    red[tid] = acc; __syncthreads();
    for (int s = 128; s > 0; s >>= 1) { if (tid < s) red[tid] += red[tid+s]; __syncthreads(); }
    if (tid == 0) g_far = red[0] / (float)(NK*NK);
}

// ---------------- zero histograms/counters ----------------
__global__ void zerohist_kernel() {
    int i = blockIdx.x * 1024 + threadIdx.x;
    if (i < NK*4096) g_hist[i] = 0u;
    if (i < NK) g_bndcnt[i] = 0u;
}

// ---------------- convert rv2 to transposed bf16 hi/lo ----------------
__global__ void convrv2_kernel(const float* __restrict__ rv2) {
    int k = blockIdx.x, n = threadIdx.x;
    float v = rv2[k*ND + n];
    unsigned short h, l;
    split_bf16(v, h, l);
    g_rv2hT[n*NH + k] = h;
    g_rv2lT[n*NH + k] = l;
}

// ---------------- kernel 1: topic GEMM 256x64xK256 + fused norm/mask/nn (R6) ----------------
__global__ void __launch_bounds__(256) topic_kernel(const float* __restrict__ f,
                                                    float* __restrict__ out_nn) {
    __shared__ float As[16*256];
    __shared__ float Bs[16*64];
    __shared__ float spart[256*8];
    __shared__ float inv_s[256];
    __shared__ float den_s[256];

    int tid = threadIdx.x;
    int tx = tid & 7, ty = tid >> 3;
    int row0 = blockIdx.x * 256;
    int b = row0 >> 9;
    int s00 = row0 & 511;

    ull acc2[8][4];
    #pragma unroll
    for (int i = 0; i < 8; i++)
        #pragma unroll
        for (int j = 0; j < 4; j++) acc2[i][j] = 0ull;
    float ssq[8];
    #pragma unroll
    for (int i = 0; i < 8; i++) ssq[i] = 0.f;

    for (int d0 = 0; d0 < ND; d0 += 16) {
        #pragma unroll
        for (int it = 0; it < 4; it++) {
            int v = tid + it*256;
            int kk = v >> 6, r4 = (v & 63) * 4;
            float4 t4 = *(const float4*)(f + ((size_t)(b*ND + d0 + kk))*NS + s00 + r4);
            *(float4*)&As[kk*256 + r4] = t4;
        }
        {
            int kk = tid >> 4, j4 = (tid & 15) * 4;
            *(float4*)&Bs[kk*64 + j4] = *(const float4*)&g_tvnp[(d0 + kk)*64 + j4];
        }
        __syncthreads();
        float a[8], an[8];
        ull bb[4], bn[4];
        {
            *(float4*)&a[0] = *(const float4*)&As[ty*8];
            *(float4*)&a[4] = *(const float4*)&As[ty*8 + 4];
            ulonglong2 q0 = *(const ulonglong2*)&Bs[tx*4];
            ulonglong2 q1 = *(const ulonglong2*)&Bs[32 + tx*4];
            bb[0]=q0.x; bb[1]=q0.y; bb[2]=q1.x; bb[3]=q1.y;
        }
        #pragma unroll
        for (int kk = 0; kk < 16; kk++) {
            if (kk < 15) {
                *(float4*)&an[0] = *(const float4*)&As[(kk+1)*256 + ty*8];
                *(float4*)&an[4] = *(const float4*)&As[(kk+1)*256 + ty*8 + 4];
                ulonglong2 q0 = *(const ulonglong2*)&Bs[(kk+1)*64 + tx*4];
                ulonglong2 q1 = *(const ulonglong2*)&Bs[(kk+1)*64 + 32 + tx*4];
                bn[0]=q0.x; bn[1]=q0.y; bn[2]=q1.x; bn[3]=q1.y;
            }
            #pragma unroll
            for (int i = 0; i < 8; i++) {
                ull ad = pack_dup(a[i]);
                #pragma unroll
                for (int j = 0; j < 4; j++) ffma2(acc2[i][j], ad, bb[j]);
            }
            if (tx == 0) {
                #pragma unroll
                for (int i = 0; i < 8; i++) ssq[i] += a[i]*a[i];
            }
            if (kk < 15) {
                #pragma unroll
                for (int i = 0; i < 8; i++) a[i] = an[i];
                #pragma unroll
                for (int j = 0; j < 4; j++) bb[j] = bn[j];
            }
        }
        __syncthreads();
    }

    if (tx == 0) {
        #pragma unroll
        for (int i = 0; i < 8; i++) {
            float iv = 1.0f / fmaxf(sqrtf(ssq[i]), 1e-12f);
            inv_s[ty*8 + i] = iv;
            g_invnorm[row0 + ty*8 + i] = iv;
        }
    }
    __syncthreads();

    float tp[8][8], amv[8][8], iv[8];
    #pragma unroll
    for (int i = 0; i < 8; i++) iv[i] = inv_s[ty*8 + i];
    #pragma unroll
    for (int i = 0; i < 8; i++) {
        #pragma unroll
        for (int j = 0; j < 4; j++) {
            float2 c = unpack2(acc2[i][j]);
            tp[i][j*2] = c.x; tp[i][j*2+1] = c.y;
        }
        float psum = 0.f;
        #pragma unroll
        for (int j = 0; j < 8; j++) {
            float t = tp[i][j] * iv[i];
            float am = (t > 0.3f) ? tp[i][j] : 0.f;
            amv[i][j] = am;
            psum += am;
        }
        spart[(ty*8 + i)*8 + tx] = psum;
    }
    __syncthreads();
    {
        float s = 0.f;
        #pragma unroll
        for (int t = 0; t < 8; t++) s += spart[tid*8 + t];
        den_s[tid] = 1.0f / ((s + 0.001f) + 1e-8f);
    }
    __syncthreads();

    #pragma unroll
    for (int i = 0; i < 8; i++) {
        int row = row0 + ty*8 + i;
        float den = den_s[ty*8 + i];
        #pragma unroll
        for (int j = 0; j < 8; j++) {
            int k = ((j >= 4) ? 32 : 0) + tx*4 + (j & 3);
            if (k < NK) {
                float v = amv[i][j] * den;
                out_nn[(size_t)row*NK + k] = v;
                g_nnT[(size_t)k*NROWS + row] = v;
                g_tpnT[(size_t)k*NROWS + row] = tp[i][j] * iv[i];
            }
        }
    }
}

// ---------------- topsel stage A: parallel histogram (grid 8 x 50) ----------------
#define TS_CHUNK 8192
__global__ void __launch_bounds__(1024) tshist_kernel() {
    __shared__ unsigned lh[4096];
    int tid = threadIdx.x;
    int k = blockIdx.y, ch = blockIdx.x;
    for (int i = tid; i < 4096; i += 1024) lh[i] = 0u;
    __syncthreads();
    const float* src = g_tpnT + (size_t)k*NROWS + ch*TS_CHUNK;
    for (int i = tid; i < TS_CHUNK; i += 1024) {
        unsigned u = __float_as_uint(src[i]);
        u = (u & 0x80000000u) ? ~u : (u | 0x80000000u);
        atomicAdd(&lh[u >> 20], 1u);
    }
    __syncthreads();
    for (int i = tid; i < 4096; i += 1024) {
        unsigned h = lh[i];
        if (h) atomicAdd(&g_hist[k*4096 + i], h);
    }
}

// ---------------- topsel stage B: threshold bin (grid 50) ----------------
__global__ void __launch_bounds__(1024) tsthresh_kernel() {
    __shared__ unsigned sscan[1024];
    __shared__ unsigned s_g;
    int tid = threadIdx.x, k = blockIdx.x;
    const unsigned* hist = g_hist + k*4096;
    unsigned gsum = hist[4*tid] + hist[4*tid+1] + hist[4*tid+2] + hist[4*tid+3];
    sscan[tid] = gsum;
    __syncthreads();
    for (int off = 1; off < 1024; off <<= 1) {
        unsigned add = (tid + off < 1024) ? sscan[tid + off] : 0u;
        __syncthreads();
        sscan[tid] += add;
        __syncthreads();
    }
    {
        unsigned Sh = sscan[tid];
        unsigned Sn = (tid < 1023) ? sscan[tid + 1] : 0u;
        if (Sh >= 32u && Sn < 32u) s_g = (unsigned)tid;
    }
    __syncthreads();
    if (tid == 0) {
        int g = (int)s_g;
        unsigned cum = (g < 1023) ? sscan[g + 1] : 0u;
        for (int bb = 4*g + 3; bb >= 4*g; bb--) {
            unsigned h = hist[bb];
            if (cum + h >= 32u) { g_T[k] = (unsigned)bb; g_cntAbove[k] = cum; break; }
            cum += h;
        }
    }
}

// ---------------- topsel stage C: parallel sum-above + boundary gather (grid 8 x 50) ----------------
__global__ void __launch_bounds__(1024) tspass2_kernel() {
    __shared__ float red[1024];
    int tid = threadIdx.x;
    int k = blockIdx.y, ch = blockIdx.x;
    unsigned T = g_T[k];
    const float* src = g_tpnT + (size_t)k*NROWS + ch*TS_CHUNK;
    float sumAbove = 0.f;
    for (int i = tid; i < TS_CHUNK; i += 1024) {
        float v = src[i];
        unsigned u = __float_as_uint(v);
        u = (u & 0x80000000u) ? ~u : (u | 0x80000000u);
        unsigned bn = u >> 20;
        if (bn > T) sumAbove += v;
        else if (bn == T) {
            unsigned p = atomicAdd(&g_bndcnt[k], 1u);
            if (p < TSEL_CAP) g_bndbuf[k*TSEL_CAP + p] = v;
        }
    }
    red[tid] = sumAbove;
    __syncthreads();
    for (int s = 512; s > 0; s >>= 1) { if (tid < s) red[tid] += red[tid+s]; __syncthreads(); }
    if (tid == 0 && red[0] != 0.f) atomicAdd(&g_sim, red[0]);
}

// ---------------- topsel stage D: pick remaining from boundary bin (grid 50) ----------------
#define PICK_SMEM ((TSEL_CAP + 1024 + 1024) * 4)
__global__ void __launch_bounds__(1024) tspick_kernel() {
    extern __shared__ float buf[];
    float* red = buf + TSEL_CAP;
    int*   ridx = (int*)(red + 1024);
    int tid = threadIdx.x, k = blockIdx.x;
    int n = (int)min(g_bndcnt[k], (unsigned)TSEL_CAP);
    for (int i = tid; i < n; i += 1024) buf[i] = g_bndbuf[k*TSEL_CAP + i];
    __syncthreads();
    int need = 32 - (int)g_cntAbove[k];
    float picked = 0.f;
    for (int it = 0; it < need; it++) {
        float lm = -FLT_MAX; int li = 0;
        for (int j = tid; j < n; j += 1024) { float x = buf[j]; if (x > lm) { lm = x; li = j; } }
        red[tid] = lm; ridx[tid] = li;
        __syncthreads();
        for (int s = 512; s > 0; s >>= 1) {
            if (tid < s && red[tid+s] > red[tid]) { red[tid] = red[tid+s]; ridx[tid] = ridx[tid+s]; }
            __syncthreads();
        }
        if (tid == 0) { picked += red[0]; buf[ridx[0]] = -FLT_MAX; }
        __syncthreads();
    }
    if (tid == 0 && need > 0) atomicAdd(&g_sim, picked);
}

// ---------------- kernel 2: rec1 GEMM 128x128xK50, relu -> bf16 hi/lo + rowsums ----------------
#define REC1_SMEM (2 * NK * 128 * 4)
__global__ void __launch_bounds__(256) rec1_kernel(const float* __restrict__ rv1) {
    extern __shared__ float sm[];
    float* As = sm;            // [k][row] 50*128
    float* Bs = sm + NK*128;   // [k][col] 50*128
    int tid = threadIdx.x;
    int tx = tid & 15, ty = tid >> 4;
    int col0 = blockIdx.x * 128;
    int row0 = blockIdx.y * 128;
    int b = row0 >> 9;

    for (int v = tid; v < 1600; v += 256) {
        int k = v >> 5, r4 = (v & 31) * 4;
        *(float4*)&As[k*128 + r4] = *(const float4*)&g_nnT[(size_t)k*NROWS + row0 + r4];
    }
    for (int v = tid; v < 1600; v += 256) {
        int k = v >> 5, j4 = (v & 31) * 4;
        *(float4*)&Bs[k*128 + j4] = *(const float4*)(rv1 + k*NH + col0 + j4);
    }
    __syncthreads();

    ull acc2[8][4];
    #pragma unroll
    for (int i = 0; i < 8; i++)
        #pragma unroll
        for (int j = 0; j < 4; j++) acc2[i][j] = 0ull;

    float a[8], an[8];
    ull bb[4], bn[4];
    {
        *(float4*)&a[0] = *(const float4*)&As[ty*8];
        *(float4*)&a[4] = *(const float4*)&As[ty*8 + 4];
        ulonglong2 q0 = *(const ulonglong2*)&Bs[tx*4];
        ulonglong2 q1 = *(const ulonglong2*)&Bs[64 + tx*4];
        bb[0]=q0.x; bb[1]=q0.y; bb[2]=q1.x; bb[3]=q1.y;
    }
    #pragma unroll 2
    for (int k = 0; k < NK; k++) {
        if (k < NK-1) {
            *(float4*)&an[0] = *(const float4*)&As[(k+1)*128 + ty*8];
            *(float4*)&an[4] = *(const float4*)&As[(k+1)*128 + ty*8 + 4];
            ulonglong2 q0 = *(const ulonglong2*)&Bs[(k+1)*128 + tx*4];
            ulonglong2 q1 = *(const ulonglong2*)&Bs[(k+1)*128 + 64 + tx*4];
            bn[0]=q0.x; bn[1]=q0.y; bn[2]=q1.x; bn[3]=q1.y;
        }
        #pragma unroll
        for (int i = 0; i < 8; i++) {
            ull ad = pack_dup(a[i]);
            #pragma unroll
            for (int j = 0; j < 4; j++) ffma2(acc2[i][j], ad, bb[j]);
        }
        if (k < NK-1) {
            #pragma unroll
            for (int i = 0; i < 8; i++) a[i] = an[i];
            #pragma unroll
            for (int j = 0; j < 4; j++) bb[j] = bn[j];
        }
    }

    float cs[8];
    #pragma unroll
    for (int j = 0; j < 8; j++) cs[j] = 0.f;

    #pragma unroll
    for (int i = 0; i < 8; i++) {
        int row = row0 + ty*8 + i;
        float o[8];
        #pragma unroll
        for (int j = 0; j < 4; j++) {
            float2 c = unpack2(acc2[i][j]);
            o[j*2]   = fmaxf(c.x, 0.f);
            o[j*2+1] = fmaxf(c.y, 0.f);
        }
        #pragma unroll
        for (int j = 0; j < 8; j++) cs[j] += o[j];
        unsigned short hh[8], ll[8];
        #pragma unroll
        for (int j = 0; j < 8; j++) split_bf16(o[j], hh[j], ll[j]);
        uint2 hv0, lv0, hv1, lv1;
        hv0.x = (unsigned)hh[0] | ((unsigned)hh[1] << 16);
        hv0.y = (unsigned)hh[2] | ((unsigned)hh[3] << 16);
        hv1.x = (unsigned)hh[4] | ((unsigned)hh[5] << 16);
        hv1.y = (unsigned)hh[6] | ((unsigned)hh[7] << 16);
        lv0.x = (unsigned)ll[0] | ((unsigned)ll[1] << 16);
        lv0.y = (unsigned)ll[2] | ((unsigned)ll[3] << 16);
        lv1.x = (unsigned)ll[4] | ((unsigned)ll[5] << 16);
        lv1.y = (unsigned)ll[6] | ((unsigned)ll[7] << 16);
        *(uint2*)&g_rec1h[(size_t)row*NH + col0 + tx*4]      = hv0;
        *(uint2*)&g_rec1h[(size_t)row*NH + col0 + 64 + tx*4] = hv1;
        *(uint2*)&g_rec1l[(size_t)row*NH + col0 + tx*4]      = lv0;
        *(uint2*)&g_rec1l[(size_t)row*NH + col0 + 64 + tx*4] = lv1;
    }

    __syncthreads();
    float* scs = As;   // 128 cols x 16 ty
    #pragma unroll
    for (int j = 0; j < 8; j++) {
        int cl = ((j >= 4) ? 64 : 0) + tx*4 + (j & 3);
        scs[cl*16 + ty] = cs[j];
    }
    __syncthreads();
    if (tid < 128) {
        float ssum = 0.f;
        #pragma unroll
        for (int t = 0; t < 16; t++) ssum += scs[tid*16 + t];
        atomicAdd(&g_h1sum[b*NH + col0 + tid], ssum);
    }
}

// ---------------- kernel 3: rec2 via mma.sync bf16x3 (HMMA), fused ae_loss ----------------
// CTA 128 rows x 128 cols, grid (2, 512). Epilogue via smem transpose for coalesced f reads.
#define R2M_SMEM (128 * 132 * 4)
__global__ void __launch_bounds__(256) rec2_mma_kernel(const float* __restrict__ f) {
    extern __shared__ float DT[];   // [col][row] 128 x 132 (pad)
    int tid = threadIdx.x;
    int wid = tid >> 5, lane = tid & 31;
    int g = lane >> 2, tg = lane & 3;
    int col0 = blockIdx.x * 128;
    int row0 = blockIdx.y * 128;
    int b = row0 >> 9;
    int s00 = row0 & 511;

    int wr = wid >> 1, wc = wid & 1;
    int rw = row0 + wr*32;
    int cw = col0 + wc*64;

    float acc[2][8][4];
    #pragma unroll
    for (int mb = 0; mb < 2; mb++)
        #pragma unroll
        for (int ns = 0; ns < 8; ns++)
            #pragma unroll
            for (int q = 0; q < 4; q++) acc[mb][ns][q] = 0.f;

    const size_t arow0 = (size_t)(rw + g) * NH;
    const size_t brow0 = (size_t)(cw + g) * NH;

    for (int k0 = 0; k0 < NH; k0 += 16) {
        int ka = k0 + tg*2;
        uint32_t ah[2][4], al[2][4];
        #pragma unroll
        for (int mb = 0; mb < 2; mb++) {
            size_t base = arow0 + (size_t)mb*16*NH + ka;
            ah[mb][0] = *(const uint32_t*)&g_rec1h[base];
            ah[mb][1] = *(const uint32_t*)&g_rec1h[base + 8*NH];
            ah[mb][2] = *(const uint32_t*)&g_rec1h[base + 8];
            ah[mb][3] = *(const uint32_t*)&g_rec1h[base + 8*NH + 8];
            al[mb][0] = *(const uint32_t*)&g_rec1l[base];
            al[mb][1] = *(const uint32_t*)&g_rec1l[base + 8*NH];
            al[mb][2] = *(const uint32_t*)&g_rec1l[base + 8];
            al[mb][3] = *(const uint32_t*)&g_rec1l[base + 8*NH + 8];
        }
        uint32_t bh[8][2];
        #pragma unroll
        for (int ns = 0; ns < 8; ns++) {
            size_t base = brow0 + (size_t)ns*8*NH + ka;
            bh[ns][0] = *(const uint32_t*)&g_rv2hT[base];
            bh[ns][1] = *(const uint32_t*)&g_rv2hT[base + 8];
        }
        #pragma unroll
        for (int mb = 0; mb < 2; mb++)
            #pragma unroll
            for (int ns = 0; ns < 8; ns++) {
                mma16816(acc[mb][ns], ah[mb], bh[ns]);
                mma16816(acc[mb][ns], al[mb], bh[ns]);
            }
        #pragma unroll
        for (int ns = 0; ns < 8; ns++) {
            size_t base = brow0 + (size_t)ns*8*NH + ka;
            bh[ns][0] = *(const uint32_t*)&g_rv2lT[base];
            bh[ns][1] = *(const uint32_t*)&g_rv2lT[base + 8];
        }
        #pragma unroll
        for (int mb = 0; mb < 2; mb++)
            #pragma unroll
            for (int ns = 0; ns < 8; ns++)
                mma16816(acc[mb][ns], ah[mb], bh[ns]);
    }

    // store D transposed into smem: DT[col][row], pad 132 (conflict-free: bank = (8*tg + g + ...)%32)
    #pragma unroll
    for (int mb = 0; mb < 2; mb++) {
        int rl = wr*32 + mb*16 + g;   // local row
        #pragma unroll
        for (int ns = 0; ns < 8; ns++) {
            int cl = wc*64 + ns*8 + tg*2 - col0 + col0;   // local col
            cl = (wc*64 + ns*8 + tg*2);
            DT[cl*132 + rl]           = acc[mb][ns][0];
            DT[(cl+1)*132 + rl]       = acc[mb][ns][1];
            DT[cl*132 + rl + 8]       = acc[mb][ns][2];
            DT[(cl+1)*132 + rl + 8]   = acc[mb][ns][3];
        }
    }
    __syncthreads();

    // ae epilogue: warp wid owns cols wid*16..+15; lanes cover rows (s) as float4 — coalesced f reads
    float in4[4];
    *(float4*)in4 = *(const float4*)&g_invnorm[row0 + lane*4];
    float ae = 0.f;
    #pragma unroll 4
    for (int cc = 0; cc < 16; cc++) {
        int cl = wid*16 + cc;
        const float* fp = f + ((size_t)(b*ND + col0 + cl))*NS + s00 + lane*4;
        float4 fv = *(const float4*)fp;
        float4 dv = *(const float4*)&DT[cl*132 + lane*4];
        float d0 = fv.x*in4[0] - dv.x;
        float d1 = fv.y*in4[1] - dv.y;
        float d2 = fv.z*in4[2] - dv.z;
        float d3 = fv.w*in4[3] - dv.w;
        ae += d0*d0 + d1*d1 + d2*d2 + d3*d3;
    }
    __syncthreads();
    DT[tid] = ae;
    __syncthreads();
    for (int st = 128; st > 0; st >>= 1) { if (tid < st) DT[tid] += DT[tid+st]; __syncthreads(); }
    if (tid == 0) atomicAdd(&g_ae, DT[0]);
}

// ---------------- g_mean = g_h1sum @ rv2 (exact fp32 path for pred) ----------------
__global__ void h1mat_kernel(const float* __restrict__ rv2) {
    __shared__ float hs[NH];
    int b = blockIdx.x, d = threadIdx.x;
    hs[d] = g_h1sum[b*NH + d];
    __syncthreads();
    float acc = 0.f;
    #pragma unroll 8
    for (int h = 0; h < NH; h++) acc += hs[h] * rv2[h*ND + d];
    g_mean[b*ND + d] = acc;
}

// ---------------- final ----------------
__global__ void final_kernel(const float* __restrict__ Wc, const float* __restrict__ bc,
                             float* __restrict__ out) {
    int tid = threadIdx.x;
    int b = tid >> 1, c = tid & 1;
    float acc = 0.f;
    for (int d = 0; d < ND; d++) acc += g_mean[b*ND + d] * Wc[d*2 + c];
    out[OUT_PRED + b*2 + c] = acc * (1.0f/512.0f) + bc[c];
    if (tid == 0) {
        out[OUT_SCAL0] = 0.0f;
        out[OUT_SIM]   = -g_sim / (float)(NK * (NB/4));
        out[OUT_FAR]   = g_far;
        out[OUT_AE]    = g_ae / (float)((size_t)NROWS * ND);
    }
}

extern "C" void kernel_launch(void* const* d_in, const int* in_sizes, int n_in,
                              void* d_out, int out_size) {
    const float* f   = (const float*)d_in[0];   // [B,D,S]
    const float* tv  = (const float*)d_in[2];   // [D,K]
    const float* rv1 = (const float*)d_in[3];   // [K,H]
    const float* rv2 = (const float*)d_in[4];   // [H,D]
    const float* Wc  = (const float*)d_in[5];   // [D,NCLS]
    const float* bc  = (const float*)d_in[6];   // [NCLS]
    float* out = (float*)d_out;

    cudaFuncSetAttribute(rec1_kernel, cudaFuncAttributeMaxDynamicSharedMemorySize, REC1_SMEM);
    cudaFuncSetAttribute(tspick_kernel, cudaFuncAttributeMaxDynamicSharedMemorySize, PICK_SMEM);
    cudaFuncSetAttribute(rec2_mma_kernel, cudaFuncAttributeMaxDynamicSharedMemorySize, R2M_SMEM);

    prep_kernel<<<1, 256>>>(tv);
    zerohist_kernel<<<200, 1024>>>();
    convrv2_kernel<<<NH, 256>>>(rv2);
    topic_kernel<<<NROWS/256, 256>>>(f, out + OUT_NN);
    tshist_kernel<<<dim3(8, NK), 1024>>>();
    tsthresh_kernel<<<NK, 1024>>>();
    tspass2_kernel<<<dim3(8, NK), 1024>>>();
    tspick_kernel<<<NK, 1024, PICK_SMEM>>>();
    rec1_kernel<<<dim3(2, 512), 256, REC1_SMEM>>>(rv1);
    rec2_mma_kernel<<<dim3(2, 512), 256, R2M_SMEM>>>(f);
    h1mat_kernel<<<NB, 256>>>(rv2);
    final_kernel<<<1, 256>>>(Wc, bc, out);
}

// round 16
// speedup vs baseline: 1.3227x; 1.3227x over previous
#include <stdint.h>
#include <cstdint>
#include <cuda_runtime.h>
#include <cuda_bf16.h>
#include <math.h>
#include <float.h>

// Problem dims
#define NB 128
#define ND 256
#define NS 512
#define NK 50
#define NH 256
#define NROWS (NB*NS)            // 65536 (b,s) rows
#define OUT_PRED 0
#define OUT_SCAL0 256
#define OUT_SIM 257
#define OUT_FAR 258
#define OUT_NN 259               // B*S*K floats
#define OUT_AE (259 + NROWS*NK)

typedef unsigned long long ull;

// ---------------- packed f32x2 helpers (FFMA2) ----------------
__device__ __forceinline__ ull pack_dup(float a) {
    ull r; asm("mov.b64 %0, {%1, %1};" : "=l"(r) : "f"(a)); return r;
}
__device__ __forceinline__ void ffma2(ull &c, ull a, ull b) {
    asm("fma.rn.f32x2 %0, %1, %2, %0;" : "+l"(c) : "l"(a), "l"(b));
}
__device__ __forceinline__ float2 unpack2(ull v) {
    float2 f; asm("mov.b64 {%0, %1}, %2;" : "=f"(f.x), "=f"(f.y) : "l"(v)); return f;
}

// ---------------- warp MMA m16n8k16 bf16 (baseline PTX, HMMA on tensor pipe) ----------------
__device__ __forceinline__ void mma16816(float* c, const uint32_t* a, const uint32_t* b) {
    asm volatile("mma.sync.aligned.m16n8k16.row.col.f32.bf16.bf16.f32 "
        "{%0,%1,%2,%3}, {%4,%5,%6,%7}, {%8,%9}, {%0,%1,%2,%3};"
        : "+f"(c[0]), "+f"(c[1]), "+f"(c[2]), "+f"(c[3])
        : "r"(a[0]), "r"(a[1]), "r"(a[2]), "r"(a[3]), "r"(b[0]), "r"(b[1]));
}

// ---------------- bf16 split helpers ----------------
__device__ __forceinline__ void split_bf16(float v, unsigned short &h, unsigned short &l) {
    __nv_bfloat16 hb = __float2bfloat16(v);
    float r = v - __bfloat162float(hb);
    __nv_bfloat16 lb = __float2bfloat16(r);
    h = *(unsigned short*)&hb;
    l = *(unsigned short*)&lb;
}

// ---------------- device scratch ----------------
#define TSEL_CAP 16384
__device__ __align__(16) float g_tvn[ND*NK];
__device__ __align__(16) float g_tvnp[ND*64];     // padded [D][64]
__device__ __align__(16) float g_invnorm[NROWS];
__device__ __align__(16) float g_tpnT[NK*NROWS];  // [K][B*S]
__device__ __align__(16) float g_nnT[NK*NROWS];   // nn transposed [K][B*S]
__device__ __align__(16) unsigned short g_rec1h[NROWS*NH];  // bf16 hi of relu(nn@rv1)
__device__ __align__(16) unsigned short g_rec1l[NROWS*NH];  // bf16 lo
__device__ __align__(16) unsigned short g_rv2hT[ND*NH];     // bf16 hi of rv2^T  [n][k]
__device__ __align__(16) unsigned short g_rv2lT[ND*NH];     // bf16 lo
__device__ __align__(16) float g_h1sum[NB*NH];    // sum_s rec1[b,s,h]
__device__ __align__(16) float g_mean[NB*ND];
__device__ __align__(16) unsigned g_hist[NK*4096];
__device__ __align__(16) float g_bndbuf[NK*TSEL_CAP];
__device__ unsigned g_bndcnt[NK];
__device__ unsigned g_T[NK];
__device__ unsigned g_cntAbove[NK];
__device__ float g_ae;
__device__ float g_sim;
__device__ float g_far;

// ---------------- kernel 0: prep ----------------
__global__ void prep_kernel(const float* __restrict__ tv) {
    __shared__ float inv[64];
    __shared__ float red[256];
    int tid = threadIdx.x;
    if (tid < NK) {
        float ss = 0.f;
        for (int d = 0; d < ND; d++) { float v = tv[d*NK + tid]; ss += v*v; }
        inv[tid] = 1.0f / fmaxf(sqrtf(ss), 1e-12f);
    }
    __syncthreads();
    for (int i = tid; i < ND*NK; i += 256) g_tvn[i] = tv[i] * inv[i % NK];
    for (int i = tid; i < NB*NH; i += 256) g_h1sum[i] = 0.f;
    if (tid == 0) { g_ae = 0.f; g_sim = 0.f; }
    __syncthreads();
    for (int i = tid; i < ND*64; i += 256) {
        int d = i >> 6, k = i & 63;
        g_tvnp[i] = (k < NK) ? g_tvn[d*NK + k] : 0.f;
    }
    float acc = 0.f;
    for (int p = tid; p < NK*NK; p += 256) {
        int i = p / NK, j = p % NK;
        float ds = 0.f;
        for (int d = 0; d < ND; d++) ds += g_tvn[d*NK + i] * g_tvn[d*NK + j];
        acc += ds - ((i == j) ? 1.0f : 0.0f);
    }
    red[tid] = acc; __syncthreads();
    for (int s = 128; s > 0; s >>= 1) { if (tid < s) red[tid] += red[tid+s]; __syncthreads(); }
    if (tid == 0) g_far = red[0] / (float)(NK*NK);
}

// ---------------- zero histograms/counters ----------------
__global__ void zerohist_kernel() {
    int i = blockIdx.x * 1024 + threadIdx.x;
    if (i < NK*4096) g_hist[i] = 0u;
    if (i < NK) g_bndcnt[i] = 0u;
}

// ---------------- convert rv2 to transposed bf16 hi/lo ----------------
__global__ void convrv2_kernel(const float* __restrict__ rv2) {
    int k = blockIdx.x, n = threadIdx.x;
    float v = rv2[k*ND + n];
    unsigned short h, l;
    split_bf16(v, h, l);
    g_rv2hT[n*NH + k] = h;
    g_rv2lT[n*NH + k] = l;
}

// ---------------- kernel 1: topic GEMM 256x64xK256 + fused norm/mask/nn ----------------
__global__ void __launch_bounds__(256, 2) topic_kernel(const float* __restrict__ f,
                                                       float* __restrict__ out_nn) {
    __shared__ float As[16*256];
    __shared__ float Bs[16*64];
    __shared__ float spart[256*8];
    __shared__ float inv_s[256];
    __shared__ float den_s[256];

    int tid = threadIdx.x;
    int tx = tid & 7, ty = tid >> 3;
    int row0 = blockIdx.x * 256;
    int b = row0 >> 9;
    int s00 = row0 & 511;

    ull acc2[8][4];
    #pragma unroll
    for (int i = 0; i < 8; i++)
        #pragma unroll
        for (int j = 0; j < 4; j++) acc2[i][j] = 0ull;
    float ssq[8];
    #pragma unroll
    for (int i = 0; i < 8; i++) ssq[i] = 0.f;

    for (int d0 = 0; d0 < ND; d0 += 16) {
        #pragma unroll
        for (int it = 0; it < 4; it++) {
            int v = tid + it*256;
            int kk = v >> 6, r4 = (v & 63) * 4;
            float4 t4 = *(const float4*)(f + ((size_t)(b*ND + d0 + kk))*NS + s00 + r4);
            *(float4*)&As[kk*256 + r4] = t4;
        }
        {
            int kk = tid >> 4, j4 = (tid & 15) * 4;
            *(float4*)&Bs[kk*64 + j4] = *(const float4*)&g_tvnp[(d0 + kk)*64 + j4];
        }
        __syncthreads();
        #pragma unroll
        for (int kk = 0; kk < 16; kk++) {
            float a[8];
            *(float4*)&a[0] = *(const float4*)&As[kk*256 + ty*8];
            *(float4*)&a[4] = *(const float4*)&As[kk*256 + ty*8 + 4];
            ulonglong2 q0 = *(const ulonglong2*)&Bs[kk*64 + tx*4];
            ulonglong2 q1 = *(const ulonglong2*)&Bs[kk*64 + 32 + tx*4];
            ull bb[4] = {q0.x, q0.y, q1.x, q1.y};
            #pragma unroll
            for (int i = 0; i < 8; i++) {
                ull ad = pack_dup(a[i]);
                #pragma unroll
                for (int j = 0; j < 4; j++) ffma2(acc2[i][j], ad, bb[j]);
            }
            if (tx == 0) {
                #pragma unroll
                for (int i = 0; i < 8; i++) ssq[i] += a[i]*a[i];
            }
        }
        __syncthreads();
    }

    if (tx == 0) {
        #pragma unroll
        for (int i = 0; i < 8; i++) {
            float iv = 1.0f / fmaxf(sqrtf(ssq[i]), 1e-12f);
            inv_s[ty*8 + i] = iv;
            g_invnorm[row0 + ty*8 + i] = iv;
        }
    }
    __syncthreads();

    // epilogue, row-at-a-time to limit registers
    #pragma unroll
    for (int i = 0; i < 8; i++) {
        float iv = inv_s[ty*8 + i];
        float psum = 0.f;
        float tp[8];
        #pragma unroll
        for (int j = 0; j < 4; j++) {
            float2 c = unpack2(acc2[i][j]);
            tp[j*2] = c.x; tp[j*2+1] = c.y;
        }
        #pragma unroll
        for (int j = 0; j < 8; j++) {
            float t = tp[j] * iv;
            psum += (t > 0.3f) ? tp[j] : 0.f;
        }
        spart[(ty*8 + i)*8 + tx] = psum;
    }
    __syncthreads();
    {
        float s = 0.f;
        #pragma unroll
        for (int t = 0; t < 8; t++) s += spart[tid*8 + t];
        den_s[tid] = 1.0f / ((s + 0.001f) + 1e-8f);
    }
    __syncthreads();

    #pragma unroll
    for (int i = 0; i < 8; i++) {
        int row = row0 + ty*8 + i;
        float iv = inv_s[ty*8 + i];
        float den = den_s[ty*8 + i];
        #pragma unroll
        for (int j = 0; j < 8; j++) {
            int k = ((j >= 4) ? 32 : 0) + tx*4 + (j & 3);
            if (k < NK) {
                float2 c = unpack2(acc2[i][j >> 1]);
                float tpv = (j & 1) ? c.y : c.x;
                float tn = tpv * iv;
                float v = ((tn > 0.3f) ? tpv : 0.f) * den;
                out_nn[(size_t)row*NK + k] = v;
                g_nnT[(size_t)k*NROWS + row] = v;
                g_tpnT[(size_t)k*NROWS + row] = tn;
            }
        }
    }
}

// ---------------- topsel stage A: parallel histogram (grid 8 x 50) ----------------
#define TS_CHUNK 8192
__global__ void __launch_bounds__(1024) tshist_kernel() {
    __shared__ unsigned lh[4096];
    int tid = threadIdx.x;
    int k = blockIdx.y, ch = blockIdx.x;
    for (int i = tid; i < 4096; i += 1024) lh[i] = 0u;
    __syncthreads();
    const float* src = g_tpnT + (size_t)k*NROWS + ch*TS_CHUNK;
    for (int i = tid; i < TS_CHUNK; i += 1024) {
        unsigned u = __float_as_uint(src[i]);
        u = (u & 0x80000000u) ? ~u : (u | 0x80000000u);
        atomicAdd(&lh[u >> 20], 1u);
    }
    __syncthreads();
    for (int i = tid; i < 4096; i += 1024) {
        unsigned h = lh[i];
        if (h) atomicAdd(&g_hist[k*4096 + i], h);
    }
}

// ---------------- topsel stage B: threshold bin (grid 50) ----------------
__global__ void __launch_bounds__(1024) tsthresh_kernel() {
    __shared__ unsigned sscan[1024];
    __shared__ unsigned s_g;
    int tid = threadIdx.x, k = blockIdx.x;
    const unsigned* hist = g_hist + k*4096;
    unsigned gsum = hist[4*tid] + hist[4*tid+1] + hist[4*tid+2] + hist[4*tid+3];
    sscan[tid] = gsum;
    __syncthreads();
    for (int off = 1; off < 1024; off <<= 1) {
        unsigned add = (tid + off < 1024) ? sscan[tid + off] : 0u;
        __syncthreads();
        sscan[tid] += add;
        __syncthreads();
    }
    {
        unsigned Sh = sscan[tid];
        unsigned Sn = (tid < 1023) ? sscan[tid + 1] : 0u;
        if (Sh >= 32u && Sn < 32u) s_g = (unsigned)tid;
    }
    __syncthreads();
    if (tid == 0) {
        int g = (int)s_g;
        unsigned cum = (g < 1023) ? sscan[g + 1] : 0u;
        for (int bb = 4*g + 3; bb >= 4*g; bb--) {
            unsigned h = hist[bb];
            if (cum + h >= 32u) { g_T[k] = (unsigned)bb; g_cntAbove[k] = cum; break; }
            cum += h;
        }
    }
}

// ---------------- topsel stage C: parallel sum-above + boundary gather (grid 8 x 50) ----------------
__global__ void __launch_bounds__(1024) tspass2_kernel() {
    __shared__ float red[1024];
    int tid = threadIdx.x;
    int k = blockIdx.y, ch = blockIdx.x;
    unsigned T = g_T[k];
    const float* src = g_tpnT + (size_t)k*NROWS + ch*TS_CHUNK;
    float sumAbove = 0.f;
    for (int i = tid; i < TS_CHUNK; i += 1024) {
        float v = src[i];
        unsigned u = __float_as_uint(v);
        u = (u & 0x80000000u) ? ~u : (u | 0x80000000u);
        unsigned bn = u >> 20;
        if (bn > T) sumAbove += v;
        else if (bn == T) {
            unsigned p = atomicAdd(&g_bndcnt[k], 1u);
            if (p < TSEL_CAP) g_bndbuf[k*TSEL_CAP + p] = v;
        }
    }
    red[tid] = sumAbove;
    __syncthreads();
    for (int s = 512; s > 0; s >>= 1) { if (tid < s) red[tid] += red[tid+s]; __syncthreads(); }
    if (tid == 0 && red[0] != 0.f) atomicAdd(&g_sim, red[0]);
}

// ---------------- topsel stage D: pick remaining from boundary bin (grid 50) ----------------
#define PICK_SMEM ((TSEL_CAP + 1024 + 1024) * 4)
__global__ void __launch_bounds__(1024) tspick_kernel() {
    extern __shared__ float buf[];
    float* red = buf + TSEL_CAP;
    int*   ridx = (int*)(red + 1024);
    int tid = threadIdx.x, k = blockIdx.x;
    int n = (int)min(g_bndcnt[k], (unsigned)TSEL_CAP);
    for (int i = tid; i < n; i += 1024) buf[i] = g_bndbuf[k*TSEL_CAP + i];
    __syncthreads();
    int need = 32 - (int)g_cntAbove[k];
    float picked = 0.f;
    for (int it = 0; it < need; it++) {
        float lm = -FLT_MAX; int li = 0;
        for (int j = tid; j < n; j += 1024) { float x = buf[j]; if (x > lm) { lm = x; li = j; } }
        red[tid] = lm; ridx[tid] = li;
        __syncthreads();
        for (int s = 512; s > 0; s >>= 1) {
            if (tid < s && red[tid+s] > red[tid]) { red[tid] = red[tid+s]; ridx[tid] = ridx[tid+s]; }
            __syncthreads();
        }
        if (tid == 0) { picked += red[0]; buf[ridx[0]] = -FLT_MAX; }
        __syncthreads();
    }
    if (tid == 0 && need > 0) atomicAdd(&g_sim, picked);
}

// ---------------- kernel 2: rec1 GEMM 128x128xK50, relu -> bf16 hi/lo + rowsums ----------------
#define REC1_SMEM (2 * NK * 128 * 4)
__global__ void __launch_bounds__(256) rec1_kernel(const float* __restrict__ rv1) {
    extern __shared__ float sm[];
    float* As = sm;            // [k][row] 50*128
    float* Bs = sm + NK*128;   // [k][col] 50*128
    int tid = threadIdx.x;
    int tx = tid & 15, ty = tid >> 4;
    int col0 = blockIdx.x * 128;
    int row0 = blockIdx.y * 128;
    int b = row0 >> 9;

    for (int v = tid; v < 1600; v += 256) {
        int k = v >> 5, r4 = (v & 31) * 4;
        *(float4*)&As[k*128 + r4] = *(const float4*)&g_nnT[(size_t)k*NROWS + row0 + r4];
    }
    for (int v = tid; v < 1600; v += 256) {
        int k = v >> 5, j4 = (v & 31) * 4;
        *(float4*)&Bs[k*128 + j4] = *(const float4*)(rv1 + k*NH + col0 + j4);
    }
    __syncthreads();

    ull acc2[8][4];
    #pragma unroll
    for (int i = 0; i < 8; i++)
        #pragma unroll
        for (int j = 0; j < 4; j++) acc2[i][j] = 0ull;

    float a[8], an[8];
    ull bb[4], bn[4];
    {
        *(float4*)&a[0] = *(const float4*)&As[ty*8];
        *(float4*)&a[4] = *(const float4*)&As[ty*8 + 4];
        ulonglong2 q0 = *(const ulonglong2*)&Bs[tx*4];
        ulonglong2 q1 = *(const ulonglong2*)&Bs[64 + tx*4];
        bb[0]=q0.x; bb[1]=q0.y; bb[2]=q1.x; bb[3]=q1.y;
    }
    #pragma unroll 2
    for (int k = 0; k < NK; k++) {
        if (k < NK-1) {
            *(float4*)&an[0] = *(const float4*)&As[(k+1)*128 + ty*8];
            *(float4*)&an[4] = *(const float4*)&As[(k+1)*128 + ty*8 + 4];
            ulonglong2 q0 = *(const ulonglong2*)&Bs[(k+1)*128 + tx*4];
            ulonglong2 q1 = *(const ulonglong2*)&Bs[(k+1)*128 + 64 + tx*4];
            bn[0]=q0.x; bn[1]=q0.y; bn[2]=q1.x; bn[3]=q1.y;
        }
        #pragma unroll
        for (int i = 0; i < 8; i++) {
            ull ad = pack_dup(a[i]);
            #pragma unroll
            for (int j = 0; j < 4; j++) ffma2(acc2[i][j], ad, bb[j]);
        }
        if (k < NK-1) {
            #pragma unroll
            for (int i = 0; i < 8; i++) a[i] = an[i];
            #pragma unroll
            for (int j = 0; j < 4; j++) bb[j] = bn[j];
        }
    }

    float cs[8];
    #pragma unroll
    for (int j = 0; j < 8; j++) cs[j] = 0.f;

    #pragma unroll
    for (int i = 0; i < 8; i++) {
        int row = row0 + ty*8 + i;
        float o[8];
        #pragma unroll
        for (int j = 0; j < 4; j++) {
            float2 c = unpack2(acc2[i][j]);
            o[j*2]   = fmaxf(c.x, 0.f);
            o[j*2+1] = fmaxf(c.y, 0.f);
        }
        #pragma unroll
        for (int j = 0; j < 8; j++) cs[j] += o[j];
        unsigned short hh[8], ll[8];
        #pragma unroll
        for (int j = 0; j < 8; j++) split_bf16(o[j], hh[j], ll[j]);
        uint2 hv0, lv0, hv1, lv1;
        hv0.x = (unsigned)hh[0] | ((unsigned)hh[1] << 16);
        hv0.y = (unsigned)hh[2] | ((unsigned)hh[3] << 16);
        hv1.x = (unsigned)hh[4] | ((unsigned)hh[5] << 16);
        hv1.y = (unsigned)hh[6] | ((unsigned)hh[7] << 16);
        lv0.x = (unsigned)ll[0] | ((unsigned)ll[1] << 16);
        lv0.y = (unsigned)ll[2] | ((unsigned)ll[3] << 16);
        lv1.x = (unsigned)ll[4] | ((unsigned)ll[5] << 16);
        lv1.y = (unsigned)ll[6] | ((unsigned)ll[7] << 16);
        *(uint2*)&g_rec1h[(size_t)row*NH + col0 + tx*4]      = hv0;
        *(uint2*)&g_rec1h[(size_t)row*NH + col0 + 64 + tx*4] = hv1;
        *(uint2*)&g_rec1l[(size_t)row*NH + col0 + tx*4]      = lv0;
        *(uint2*)&g_rec1l[(size_t)row*NH + col0 + 64 + tx*4] = lv1;
    }

    __syncthreads();
    float* scs = As;   // 128 cols x 16 ty
    #pragma unroll
    for (int j = 0; j < 8; j++) {
        int cl = ((j >= 4) ? 64 : 0) + tx*4 + (j & 3);
        scs[cl*16 + ty] = cs[j];
    }
    __syncthreads();
    if (tid < 128) {
        float ssum = 0.f;
        #pragma unroll
        for (int t = 0; t < 16; t++) ssum += scs[tid*16 + t];
        atomicAdd(&g_h1sum[b*NH + col0 + tid], ssum);
    }
}

// ---------------- kernel 3: rec2 via mma.sync bf16x3 (HMMA), smem-staged tiles ----------------
// CTA 128 rows x 128 cols, grid (2, 512). K chunks of 64 staged in smem (pad 72).
// 8 warps: wr = wid>>1 (row group of 32), wc = wid&1 (col group of 64).
#define R2M_SMEM (4 * 128 * 72 * 2)   // 73728 B
__global__ void __launch_bounds__(256) rec2_mma_kernel(const float* __restrict__ f) {
    extern __shared__ unsigned short ts[];
    unsigned short* Ahs = ts;                 // [128][72]
    unsigned short* Als = ts + 128*72;
    unsigned short* Bhs = ts + 2*128*72;
    unsigned short* Bls = ts + 3*128*72;
    int tid = threadIdx.x;
    int wid = tid >> 5, lane = tid & 31;
    int g = lane >> 2, tg = lane & 3;
    int col0 = blockIdx.x * 128;
    int row0 = blockIdx.y * 128;
    int b = row0 >> 9;
    int s00 = row0 & 511;
    int wr = wid >> 1, wc = wid & 1;

    float acc[2][8][4];
    #pragma unroll
    for (int mb = 0; mb < 2; mb++)
        #pragma unroll
        for (int ns = 0; ns < 8; ns++)
            #pragma unroll
            for (int q = 0; q < 4; q++) acc[mb][ns][q] = 0.f;

    for (int k0 = 0; k0 < NH; k0 += 64) {
        // stage tiles: 128 rows x 64 bf16 per matrix, coalesced 128B rows
        for (int v = tid; v < 1024; v += 256) {
            int r = v >> 3, seg = (v & 7) * 8;
            size_t ga = (size_t)(row0 + r)*NH + k0 + seg;
            size_t gb = (size_t)(col0 + r)*NH + k0 + seg;
            *(uint4*)&Ahs[r*72 + seg] = *(const uint4*)&g_rec1h[ga];
            *(uint4*)&Als[r*72 + seg] = *(const uint4*)&g_rec1l[ga];
            *(uint4*)&Bhs[r*72 + seg] = *(const uint4*)&g_rv2hT[gb];
            *(uint4*)&Bls[r*72 + seg] = *(const uint4*)&g_rv2lT[gb];
        }
        __syncthreads();
        #pragma unroll
        for (int kk = 0; kk < 4; kk++) {
            int ka = kk*16 + tg*2;
            uint32_t ah[2][4], al[2][4];
            #pragma unroll
            for (int mb = 0; mb < 2; mb++) {
                int base = (wr*32 + mb*16 + g)*72 + ka;
                ah[mb][0] = *(const uint32_t*)&Ahs[base];
                ah[mb][1] = *(const uint32_t*)&Ahs[base + 8*72];
                ah[mb][2] = *(const uint32_t*)&Ahs[base + 8];
                ah[mb][3] = *(const uint32_t*)&Ahs[base + 8*72 + 8];
                al[mb][0] = *(const uint32_t*)&Als[base];
                al[mb][1] = *(const uint32_t*)&Als[base + 8*72];
                al[mb][2] = *(const uint32_t*)&Als[base + 8];
                al[mb][3] = *(const uint32_t*)&Als[base + 8*72 + 8];
            }
            uint32_t bf[8][2];
            #pragma unroll
            for (int ns = 0; ns < 8; ns++) {
                int bbase = (wc*64 + ns*8 + g)*72 + ka;
                bf[ns][0] = *(const uint32_t*)&Bhs[bbase];
                bf[ns][1] = *(const uint32_t*)&Bhs[bbase + 8];
            }
            #pragma unroll
            for (int mb = 0; mb < 2; mb++)
                #pragma unroll
                for (int ns = 0; ns < 8; ns++) {
                    mma16816(acc[mb][ns], ah[mb], bf[ns]);
                    mma16816(acc[mb][ns], al[mb], bf[ns]);
                }
            #pragma unroll
            for (int ns = 0; ns < 8; ns++) {
                int bbase = (wc*64 + ns*8 + g)*72 + ka;
                bf[ns][0] = *(const uint32_t*)&Bls[bbase];
                bf[ns][1] = *(const uint32_t*)&Bls[bbase + 8];
            }
            #pragma unroll
            for (int mb = 0; mb < 2; mb++)
                #pragma unroll
                for (int ns = 0; ns < 8; ns++)
                    mma16816(acc[mb][ns], ah[mb], bf[ns]);
        }
        __syncthreads();
    }

    // epilogue: transpose D into smem (reuse tile area) for coalesced f reads
    float* DT = (float*)ts;   // [col][row] 128 x 132 = 67584 B <= 73728
    #pragma unroll
    for (int mb = 0; mb < 2; mb++) {
        int rl = wr*32 + mb*16 + g;
        #pragma unroll
        for (int ns = 0; ns < 8; ns++) {
            int cl = wc*64 + ns*8 + tg*2;
            DT[cl*132 + rl]           = acc[mb][ns][0];
            DT[(cl+1)*132 + rl]       = acc[mb][ns][1];
            DT[cl*132 + rl + 8]       = acc[mb][ns][2];
            DT[(cl+1)*132 + rl + 8]   = acc[mb][ns][3];
        }
    }
    __syncthreads();

    float in4[4];
    *(float4*)in4 = *(const float4*)&g_invnorm[row0 + lane*4];
    float ae = 0.f;
    #pragma unroll 4
    for (int cc = 0; cc < 16; cc++) {
        int cl = wid*16 + cc;
        const float* fp = f + ((size_t)(b*ND + col0 + cl))*NS + s00 + lane*4;
        float4 fv = *(const float4*)fp;
        float4 dv = *(const float4*)&DT[cl*132 + lane*4];
        float d0 = fv.x*in4[0] - dv.x;
        float d1 = fv.y*in4[1] - dv.y;
        float d2 = fv.z*in4[2] - dv.z;
        float d3 = fv.w*in4[3] - dv.w;
        ae += d0*d0 + d1*d1 + d2*d2 + d3*d3;
    }
    __syncthreads();
    DT[tid] = ae;
    __syncthreads();
    for (int st = 128; st > 0; st >>= 1) { if (tid < st) DT[tid] += DT[tid+st]; __syncthreads(); }
    if (tid == 0) atomicAdd(&g_ae, DT[0]);
}

// ---------------- g_mean = g_h1sum @ rv2 (exact fp32 path for pred) ----------------
__global__ void h1mat_kernel(const float* __restrict__ rv2) {
    __shared__ float hs[NH];
    int b = blockIdx.x, d = threadIdx.x;
    hs[d] = g_h1sum[b*NH + d];
    __syncthreads();
    float acc = 0.f;
    #pragma unroll 8
    for (int h = 0; h < NH; h++) acc += hs[h] * rv2[h*ND + d];
    g_mean[b*ND + d] = acc;
}

// ---------------- final ----------------
__global__ void final_kernel(const float* __restrict__ Wc, const float* __restrict__ bc,
                             float* __restrict__ out) {
    int tid = threadIdx.x;
    int b = tid >> 1, c = tid & 1;
    float acc = 0.f;
    for (int d = 0; d < ND; d++) acc += g_mean[b*ND + d] * Wc[d*2 + c];
    out[OUT_PRED + b*2 + c] = acc * (1.0f/512.0f) + bc[c];
    if (tid == 0) {
        out[OUT_SCAL0] = 0.0f;
        out[OUT_SIM]   = -g_sim / (float)(NK * (NB/4));
        out[OUT_FAR]   = g_far;
        out[OUT_AE]    = g_ae / (float)((size_t)NROWS * ND);
    }
}

extern "C" void kernel_launch(void* const* d_in, const int* in_sizes, int n_in,
                              void* d_out, int out_size) {
    const float* f   = (const float*)d_in[0];   // [B,D,S]
    const float* tv  = (const float*)d_in[2];   // [D,K]
    const float* rv1 = (const float*)d_in[3];   // [K,H]
    const float* rv2 = (const float*)d_in[4];   // [H,D]
    const float* Wc  = (const float*)d_in[5];   // [D,NCLS]
    const float* bc  = (const float*)d_in[6];   // [NCLS]
    float* out = (float*)d_out;

    cudaFuncSetAttribute(rec1_kernel, cudaFuncAttributeMaxDynamicSharedMemorySize, REC1_SMEM);
    cudaFuncSetAttribute(tspick_kernel, cudaFuncAttributeMaxDynamicSharedMemorySize, PICK_SMEM);
    cudaFuncSetAttribute(rec2_mma_kernel, cudaFuncAttributeMaxDynamicSharedMemorySize, R2M_SMEM);

    prep_kernel<<<1, 256>>>(tv);
    zerohist_kernel<<<200, 1024>>>();
    convrv2_kernel<<<NH, 256>>>(rv2);
    topic_kernel<<<NROWS/256, 256>>>(f, out + OUT_NN);
    tshist_kernel<<<dim3(8, NK), 1024>>>();
    tsthresh_kernel<<<NK, 1024>>>();
    tspass2_kernel<<<dim3(8, NK), 1024>>>();
    tspick_kernel<<<NK, 1024, PICK_SMEM>>>();
    rec1_kernel<<<dim3(2, 512), 256, REC1_SMEM>>>(rv1);
    rec2_mma_kernel<<<dim3(2, 512), 256, R2M_SMEM>>>(f);
    h1mat_kernel<<<NB, 256>>>(rv2);
    final_kernel<<<1, 256>>>(Wc, bc, out);
}